// round 1
// baseline (speedup 1.0000x reference)
#include <cuda_runtime.h>

// ACT-LSTM (adaptive computation time) — persistent single-kernel implementation.
// Shapes fixed for this problem: I=1024, H=2048, O=1024, 4H=8192, MAX_STEPS=20.
//
// Inputs (metadata order):
//  0: x[1024]  1: h[2048]  2: c[2048]  3: W_ih[8192*1025]  4: W_hh[8192*2048]
//  5: b_ih[8192]  6: b_hh[8192]  7: w_halt[2048]  8: b_halt[1]
//  9: W_out[1024*2048]  10: b_out[1024]
// Output (5121 floats): out[0:1024]=W_out@h*+b_out, [1024:3072]=h*, [3072:5120]=c*,
//  [5120]=ponder (= 0-indexed halting step).

#define NBLOCK 148
#define NTHREAD 512
#define WPB (NTHREAD / 32)            // warps per block = 16
#define TOTAL_WARPS (NBLOCK * WPB)    // 2368
#define HDIM 2048
#define IDIM 1024
#define ODIM 1024
#define G4 (4 * HDIM)                 // 8192
#define MAX_STEPS 20

// -------- device scratch (no allocation allowed) --------
__device__ float g_gx[G4];       // W_ih[:,1:]@x + b_ih + b_hh (step-invariant)
__device__ float g_wih0[G4];     // W_ih[:,0] (flag column, added only at t=0)
__device__ float g_gates[G4];
__device__ float g_h[HDIM];
__device__ float g_c[HDIM];
__device__ float g_cum;
__device__ volatile int g_halt;
__device__ int g_tstep;

// -------- manual grid barrier --------
__device__ unsigned g_bar_count = 0;
__device__ volatile unsigned g_bar_gen = 0;

__device__ __forceinline__ void grid_sync() {
    __syncthreads();
    if (threadIdx.x == 0) {
        __threadfence();                       // release prior global writes
        unsigned gen = g_bar_gen;
        if (atomicAdd(&g_bar_count, 1u) == NBLOCK - 1) {
            g_bar_count = 0u;
            __threadfence();
            g_bar_gen = gen + 1u;
        } else {
            while (g_bar_gen == gen) { }
            __threadfence();                   // acquire
        }
    }
    __syncthreads();
}

__device__ __forceinline__ float warp_reduce(float v) {
    #pragma unroll
    for (int off = 16; off; off >>= 1) v += __shfl_xor_sync(0xffffffffu, v, off);
    return v;
}

__device__ __forceinline__ float sigmoidf_(float x) {
    return 1.0f / (1.0f + __expf(-x));
}

__global__ __launch_bounds__(NTHREAD, 1)
void act_lstm_kernel(const float* __restrict__ x,
                     const float* __restrict__ h0,
                     const float* __restrict__ c0,
                     const float* __restrict__ W_ih,
                     const float* __restrict__ W_hh,
                     const float* __restrict__ b_ih,
                     const float* __restrict__ b_hh,
                     const float* __restrict__ w_halt,
                     const float* __restrict__ b_halt,
                     const float* __restrict__ W_out,
                     const float* __restrict__ b_out,
                     float* __restrict__ out) {
    __shared__ float sh[HDIM];     // staging for x (phase 0) then h (per step)
    __shared__ float s_red[WPB];

    const int tid   = threadIdx.x;
    const int lane  = tid & 31;
    const int warp  = tid >> 5;
    const int gwarp = blockIdx.x * WPB + warp;

    // ---------------- phase 0: init state + step-invariant gx ----------------
    if (blockIdx.x == 0 && tid == 0) {
        g_cum = 0.0f;
        g_halt = 0;
        g_tstep = MAX_STEPS - 1;
    }
    for (int j = blockIdx.x * NTHREAD + tid; j < HDIM; j += NBLOCK * NTHREAD) {
        g_h[j] = h0[j];
        g_c[j] = c0[j];
    }
    // stage x in shared
    for (int j = tid; j < IDIM; j += NTHREAD) sh[j] = x[j];
    __syncthreads();

    // gx[r] = W_ih[r,1:1025] . x  + b_ih[r] + b_hh[r] ; wih0[r] = W_ih[r,0]
    for (int r = gwarp; r < G4; r += TOTAL_WARPS) {
        const float* wr = W_ih + (size_t)r * (IDIM + 1);
        float acc = 0.0f;
        #pragma unroll 8
        for (int k = lane; k < IDIM; k += 32) acc += __ldg(wr + 1 + k) * sh[k];
        acc = warp_reduce(acc);
        if (lane == 0) {
            g_gx[r]   = acc + b_ih[r] + b_hh[r];
            g_wih0[r] = wr[0];
        }
    }
    grid_sync();

    // ---------------- adaptive step loop ----------------
    for (int t = 0; t < MAX_STEPS; ++t) {
        // stage h in shared
        for (int j = tid; j < HDIM; j += NTHREAD) sh[j] = g_h[j];
        __syncthreads();

        const float flag = (t == 0) ? 1.0f : 0.0f;

        // phase A: gates[r] = gx[r] + flag*wih0[r] + W_hh[r,:] . h
        for (int r = gwarp; r < G4; r += TOTAL_WARPS) {
            const float4* wr = (const float4*)(W_hh + (size_t)r * HDIM);
            const float4* hv = (const float4*)sh;
            float acc = 0.0f;
            #pragma unroll 16
            for (int k = lane; k < HDIM / 4; k += 32) {
                float4 w = __ldg(wr + k);
                float4 h4 = hv[k];
                acc += w.x * h4.x + w.y * h4.y + w.z * h4.z + w.w * h4.w;
            }
            acc = warp_reduce(acc);
            if (lane == 0) g_gates[r] = g_gx[r] + flag * g_wih0[r] + acc;
        }
        grid_sync();

        // phase B (block 0 only): activations, state update, halting decision.
        // Fixed traversal order -> deterministic fp result every call.
        if (blockIdx.x == 0) {
            float part = 0.0f;
            for (int j = tid; j < HDIM; j += NTHREAD) {
                float gi = g_gates[j];
                float gf = g_gates[HDIM + j];
                float gg = g_gates[2 * HDIM + j];
                float go = g_gates[3 * HDIM + j];
                float cn = sigmoidf_(gf) * g_c[j] + sigmoidf_(gi) * tanhf(gg);
                float hn = sigmoidf_(go) * tanhf(cn);
                g_c[j] = cn;
                g_h[j] = hn;
                part += w_halt[j] * hn;
            }
            part = warp_reduce(part);
            if (lane == 0) s_red[warp] = part;
            __syncthreads();
            if (tid == 0) {
                float dot = 0.0f;
                #pragma unroll
                for (int w2 = 0; w2 < WPB; ++w2) dot += s_red[w2];
                float p = sigmoidf_(dot + b_halt[0]);
                float cum = g_cum + p;
                g_cum = cum;
                const float thresh = 1.0f - 0.01f;
                if (cum >= thresh || t == MAX_STEPS - 1) {
                    g_tstep = t;
                    __threadfence();
                    g_halt = 1;
                }
            }
        }
        grid_sync();
        if (g_halt) break;
    }

    // ---------------- epilogue: output = W_out @ h + b_out; emit h, c, ponder ----
    __syncthreads();
    for (int j = tid; j < HDIM; j += NTHREAD) sh[j] = g_h[j];
    __syncthreads();

    for (int r = gwarp; r < ODIM; r += TOTAL_WARPS) {
        const float4* wr = (const float4*)(W_out + (size_t)r * HDIM);
        const float4* hv = (const float4*)sh;
        float acc = 0.0f;
        #pragma unroll 16
        for (int k = lane; k < HDIM / 4; k += 32) {
            float4 w = __ldg(wr + k);
            float4 h4 = hv[k];
            acc += w.x * h4.x + w.y * h4.y + w.z * h4.z + w.w * h4.w;
        }
        acc = warp_reduce(acc);
        if (lane == 0) out[r] = acc + b_out[r];
    }

    for (int j = blockIdx.x * NTHREAD + tid; j < HDIM; j += NBLOCK * NTHREAD) {
        out[ODIM + j]        = g_h[j];
        out[ODIM + HDIM + j] = g_c[j];
    }
    if (blockIdx.x == 0 && tid == 0) {
        // ponder = number of non-halting valid steps = halting step index (0-based)
        out[ODIM + 2 * HDIM] = (float)g_tstep;
    }
}

extern "C" void kernel_launch(void* const* d_in, const int* in_sizes, int n_in,
                              void* d_out, int out_size) {
    (void)in_sizes; (void)n_in; (void)out_size;
    const float* x      = (const float*)d_in[0];
    const float* h0     = (const float*)d_in[1];
    const float* c0     = (const float*)d_in[2];
    const float* W_ih   = (const float*)d_in[3];
    const float* W_hh   = (const float*)d_in[4];
    const float* b_ih   = (const float*)d_in[5];
    const float* b_hh   = (const float*)d_in[6];
    const float* w_halt = (const float*)d_in[7];
    const float* b_halt = (const float*)d_in[8];
    const float* W_out  = (const float*)d_in[9];
    const float* b_out  = (const float*)d_in[10];
    float* out = (float*)d_out;

    act_lstm_kernel<<<NBLOCK, NTHREAD>>>(x, h0, c0, W_ih, W_hh, b_ih, b_hh,
                                         w_halt, b_halt, W_out, b_out, out);
}

// round 2
// speedup vs baseline: 1.4298x; 1.4298x over previous
#include <cuda_runtime.h>

// ACT-LSTM persistent kernel, v2.
// Key structure vs v1:
//  - Step-0 gates fused: one pass reads W_ih and W_hh together (max MLP).
//  - Phase B (activations + halt decision) computed REDUNDANTLY by every block
//    on block-local shared h/c (identical fp ops -> identical halt decision),
//    eliminating the serial block-0 phase and one grid barrier per step.
//  - g_gates double-buffered so only ONE grid barrier per step is needed.
//  - Epilogue is barrier-free (each block has final h in shared).
//
// I=1024, H=2048, O=1024, 4H=8192, MAX_STEPS=20.

#define NBLOCK 148
#define NTHREAD 512
#define WPB (NTHREAD / 32)            // 16 warps/block
#define TOTAL_WARPS (NBLOCK * WPB)    // 2368
#define HDIM 2048
#define IDIM 1024
#define ODIM 1024
#define G4 (4 * HDIM)                 // 8192
#define MAX_STEPS 20

// -------- device scratch (no allocation allowed) --------
__device__ float g_gates[2][G4];      // double-buffered gate pre-activations

// -------- manual grid barrier --------
__device__ unsigned g_bar_count = 0;
__device__ volatile unsigned g_bar_gen = 0;

__device__ __forceinline__ void grid_sync() {
    __syncthreads();
    if (threadIdx.x == 0) {
        __threadfence();                       // release prior global writes
        unsigned gen = g_bar_gen;
        if (atomicAdd(&g_bar_count, 1u) == NBLOCK - 1) {
            g_bar_count = 0u;
            __threadfence();
            g_bar_gen = gen + 1u;
        } else {
            while (g_bar_gen == gen) { __nanosleep(32); }
            __threadfence();                   // acquire
        }
    }
    __syncthreads();
}

__device__ __forceinline__ float warp_reduce(float v) {
    #pragma unroll
    for (int off = 16; off; off >>= 1) v += __shfl_xor_sync(0xffffffffu, v, off);
    return v;
}

__device__ __forceinline__ float sigmoidf_(float x) {
    return 1.0f / (1.0f + __expf(-x));
}

__global__ __launch_bounds__(NTHREAD, 1)
void act_lstm_kernel(const float* __restrict__ x,
                     const float* __restrict__ h0,
                     const float* __restrict__ c0,
                     const float* __restrict__ W_ih,
                     const float* __restrict__ W_hh,
                     const float* __restrict__ b_ih,
                     const float* __restrict__ b_hh,
                     const float* __restrict__ w_halt,
                     const float* __restrict__ b_halt,
                     const float* __restrict__ W_out,
                     const float* __restrict__ b_out,
                     float* __restrict__ gx,      // scratch via out tail? no: device global below
                     float* __restrict__ out) {
    // block-local replicated state
    __shared__ float sh_h[HDIM];
    __shared__ float sh_c[HDIM];
    __shared__ float sh_x[IDIM];
    __shared__ float s_red[WPB];

    const int tid   = threadIdx.x;
    const int lane  = tid & 31;
    const int warp  = tid >> 5;
    const int gwarp = blockIdx.x * WPB + warp;

    // ---- init local state ----
    for (int j = tid; j < HDIM; j += NTHREAD) {
        sh_h[j] = h0[j];
        sh_c[j] = c0[j];
    }
    for (int j = tid; j < IDIM; j += NTHREAD) sh_x[j] = x[j];
    const float bh = b_halt[0];
    __syncthreads();

    // ---- fused phase: gates(t=0) = W_ih@[1,x] + b_ih + b_hh + W_hh@h0 ----
    // also stores gx[r] = W_ih[r,1:]@x + b_ih + b_hh for later steps.
    for (int r = gwarp; r < G4; r += TOTAL_WARPS) {
        const float*  wi = W_ih + (size_t)r * (IDIM + 1);
        const float4* wh = (const float4*)(W_hh + (size_t)r * HDIM);
        const float4* hv = (const float4*)sh_h;
        float a_ih = 0.0f;
        #pragma unroll 8
        for (int k = lane; k < IDIM; k += 32) a_ih += __ldg(wi + 1 + k) * sh_x[k];
        float a_hh = 0.0f;
        #pragma unroll 16
        for (int k = lane; k < HDIM / 4; k += 32) {
            float4 w = __ldg(wh + k);
            float4 h4 = hv[k];
            a_hh += w.x * h4.x + w.y * h4.y + w.z * h4.z + w.w * h4.w;
        }
        a_ih = warp_reduce(a_ih);
        a_hh = warp_reduce(a_hh);
        if (lane == 0) {
            float base = a_ih + b_ih[r] + b_hh[r];
            gx[r] = base;
            g_gates[0][r] = base + wi[0] + a_hh;   // flag column active at t=0
        }
    }
    grid_sync();

    // ---- adaptive loop: ONE grid barrier per step ----
    float cum = 0.0f;
    int   halted_t = MAX_STEPS - 1;
    int   buf = 0;

    for (int t = 0; t < MAX_STEPS; ++t) {
        // phase B (every block, redundant, block-local): activations + halt
        const float* gt = g_gates[buf];
        float part = 0.0f;
        for (int j = tid; j < HDIM; j += NTHREAD) {
            float gi = gt[j];
            float gf = gt[HDIM + j];
            float gg = gt[2 * HDIM + j];
            float go = gt[3 * HDIM + j];
            float cn = sigmoidf_(gf) * sh_c[j] + sigmoidf_(gi) * tanhf(gg);
            float hn = sigmoidf_(go) * tanhf(cn);
            sh_c[j] = cn;
            sh_h[j] = hn;
            part += w_halt[j] * hn;
        }
        part = warp_reduce(part);
        if (lane == 0) s_red[warp] = part;
        __syncthreads();
        float dot = 0.0f;
        #pragma unroll
        for (int w2 = 0; w2 < WPB; ++w2) dot += s_red[w2];
        float p = sigmoidf_(dot + bh);
        cum += p;
        if (cum >= 0.99f || t == MAX_STEPS - 1) { halted_t = t; break; }

        // phase A for step t+1: gates = gx + W_hh @ h   (h is block-local shared)
        buf ^= 1;
        float* gn = g_gates[buf];
        for (int r = gwarp; r < G4; r += TOTAL_WARPS) {
            const float4* wh = (const float4*)(W_hh + (size_t)r * HDIM);
            const float4* hv = (const float4*)sh_h;
            float acc = 0.0f;
            #pragma unroll 16
            for (int k = lane; k < HDIM / 4; k += 32) {
                float4 w = __ldg(wh + k);
                float4 h4 = hv[k];
                acc += w.x * h4.x + w.y * h4.y + w.z * h4.z + w.w * h4.w;
            }
            acc = warp_reduce(acc);
            if (lane == 0) gn[r] = gx[r] + acc;
        }
        grid_sync();
        __syncthreads();   // ensure s_red reuse + sh_h stable (grid_sync has one, keep for clarity)
    }

    // ---- epilogue (barrier-free): out = W_out @ h + b_out; emit h, c, ponder ----
    __syncthreads();
    for (int r = gwarp; r < ODIM; r += TOTAL_WARPS) {
        const float4* wr = (const float4*)(W_out + (size_t)r * HDIM);
        const float4* hv = (const float4*)sh_h;
        float acc = 0.0f;
        #pragma unroll 16
        for (int k = lane; k < HDIM / 4; k += 32) {
            float4 w = __ldg(wr + k);
            float4 h4 = hv[k];
            acc += w.x * h4.x + w.y * h4.y + w.z * h4.z + w.w * h4.w;
        }
        acc = warp_reduce(acc);
        if (lane == 0) out[r] = acc + b_out[r];
    }

    if (blockIdx.x == 0) {
        for (int j = tid; j < HDIM; j += NTHREAD) {
            out[ODIM + j]        = sh_h[j];
            out[ODIM + HDIM + j] = sh_c[j];
        }
        if (tid == 0) out[ODIM + 2 * HDIM] = (float)halted_t;
    }
}

// gx scratch lives in device global (no allocation allowed)
__device__ float g_gx_buf[G4];

extern "C" void kernel_launch(void* const* d_in, const int* in_sizes, int n_in,
                              void* d_out, int out_size) {
    (void)in_sizes; (void)n_in; (void)out_size;
    const float* x      = (const float*)d_in[0];
    const float* h0     = (const float*)d_in[1];
    const float* c0     = (const float*)d_in[2];
    const float* W_ih   = (const float*)d_in[3];
    const float* W_hh   = (const float*)d_in[4];
    const float* b_ih   = (const float*)d_in[5];
    const float* b_hh   = (const float*)d_in[6];
    const float* w_halt = (const float*)d_in[7];
    const float* b_halt = (const float*)d_in[8];
    const float* W_out  = (const float*)d_in[9];
    const float* b_out  = (const float*)d_in[10];
    float* out = (float*)d_out;

    float* gx_ptr = nullptr;
    cudaGetSymbolAddress((void**)&gx_ptr, g_gx_buf);

    act_lstm_kernel<<<NBLOCK, NTHREAD>>>(x, h0, c0, W_ih, W_hh, b_ih, b_hh,
                                         w_halt, b_halt, W_out, b_out,
                                         gx_ptr, out);
}